// round 6
// baseline (speedup 1.0000x reference)
#include <cuda_runtime.h>
#include <cuda_bf16.h>
#include <cstdint>
#include <cub/cub.cuh>

// Problem geometry: B=64 samples, n = 512*512 = 2^18 elements per sample.
#define BATCH 64
#define LOGN  18
#define NPS   (1u << LOGN)              // 262144
#define SMASK (NPS - 1u)                // 0x3FFFF
#define TOTN  (BATCH * NPS)             // 16777216

// MSD bucket sort config for the (uniform) shuffle keys.
#define HB        11                    // top bits -> 2048 buckets/segment
#define NBUCK     (1u << HB)            // 2048
#define TOTBUCK   (BATCH * NBUCK)       // 131072
#define CAP       256u                  // bucket capacity (mean 128, sigma ~11)
#define TILE      16384u                // elements per scatter block
#define SCAT_T    512                   // scatter block threads

// ---------------------------------------------------------------------------
// Static device scratch (allocation-free per harness rules).
// ---------------------------------------------------------------------------
__device__ __align__(256) unsigned long long g_bufA[TOTN];            // 128 MB (rank sort)
__device__ __align__(256) unsigned long long g_bufB[TOTN];            // 128 MB (rank sort alt)
__device__ __align__(256) unsigned long long g_scratch[TOTBUCK*CAP];  // 268 MB (bucketed shuffle keys)
__device__ __align__(256) unsigned int       g_rank2[TOTN];           // 64 MB: 2*avg_rank per orig idx
__device__ __align__(256) unsigned int       g_pi1[TOTN];             // 64 MB: realized perm round 1
__device__ __align__(256) unsigned int       g_pi2[TOTN];             // 64 MB: realized perm round 2
__device__ __align__(256) unsigned int       g_cnt[TOTBUCK];          // bucket counts
__device__ __align__(256) unsigned int       g_off[TOTBUCK];          // scanned output offsets
__device__ __align__(256) unsigned char      g_temp [64u*1024u*1024u];// CUB radix temp
__device__ __align__(256) unsigned char      g_temp2[1u*1024u*1024u]; // CUB scan temp
__device__ unsigned long long g_sum2[BATCH];
__device__ unsigned int       g_npos[BATCH];

struct SubKeys { uint2 sk[BATCH]; };

// ---------------------------------------------------------------------------
// Threefry-2x32 (20 rounds), matches JAX's threefry2x32_p.
// ---------------------------------------------------------------------------
__host__ __device__ __forceinline__ void tf2x32(uint32_t k0, uint32_t k1,
                                                uint32_t x0, uint32_t x1,
                                                uint32_t& o0, uint32_t& o1)
{
    uint32_t ks2 = k0 ^ k1 ^ 0x1BD11BDAu;
    x0 += k0; x1 += k1;
#define TFR(r) { x0 += x1; x1 = (x1 << (r)) | (x1 >> (32 - (r))); x1 ^= x0; }
    TFR(13) TFR(15) TFR(26) TFR(6)
    x0 += k1;  x1 += ks2 + 1u;
    TFR(17) TFR(29) TFR(16) TFR(24)
    x0 += ks2; x1 += k0 + 2u;
    TFR(13) TFR(15) TFR(26) TFR(6)
    x0 += k0;  x1 += k1 + 3u;
    TFR(17) TFR(29) TFR(16) TFR(24)
    x0 += k1;  x1 += ks2 + 4u;
    TFR(13) TFR(15) TFR(26) TFR(6)
    x0 += ks2; x1 += k0 + 5u;
#undef TFR
    o0 = x0; o1 = x1;
}

// ---------------------------------------------------------------------------
// Branch A: rank phase (unchanged from the passing version).
// ---------------------------------------------------------------------------
__global__ void gen_rank_keys(const float* __restrict__ pred,
                              unsigned long long* __restrict__ out)
{
    unsigned int j = blockIdx.x * blockDim.x + threadIdx.x;
    uint32_t u = __float_as_uint(pred[j]);
    u = (u >> 31) ? ~u : (u | 0x80000000u);   // totally-ordered ascending float bits
    unsigned long long seg = (unsigned long long)(j >> LOGN);
    out[j] = (seg << 50) | ((unsigned long long)u << 18) | (j & SMASK);
}

__global__ void rank_kernel(const unsigned long long* __restrict__ KR,
                            unsigned int* __restrict__ rank2)
{
    unsigned int j = blockIdx.x * blockDim.x + threadIdx.x;
    unsigned long long k = KR[j];
    unsigned long long hk = k >> 18;          // seg+value bits: runs never cross segments
    unsigned int s = j, e = j;
    while (s > 0u && (KR[s - 1u] >> 18) == hk) --s;       // ties rare & short
    while (e + 1u < TOTN && (KR[e + 1u] >> 18) == hk) ++e;
    unsigned int orig = (unsigned int)k & SMASK;
    unsigned int twice_rank = (s & SMASK) + (e & SMASK) + 2u;
    rank2[(j & ~SMASK) | orig] = twice_rank;
}

// ---------------------------------------------------------------------------
// Branch B: custom 2-pass MSD realization of the stable shuffle argsorts.
// ---------------------------------------------------------------------------
__global__ void zero_u32(unsigned int* __restrict__ p, unsigned int n)
{
    unsigned int i = blockIdx.x * blockDim.x + threadIdx.x;
    if (i < n) p[i] = 0u;
}

// Scatter: generate threefry bits on the fly, bucket by top-11 bits into
// fixed-capacity (256) per-bucket regions. Within-bucket order is arbitrary
// (atomic); the bucket-sort pass makes the result deterministic & stable.
__global__ void scatter_kernel(SubKeys sks,
                               unsigned long long* __restrict__ scratch,
                               unsigned int* __restrict__ gcnt)
{
    extern __shared__ unsigned int sm[];
    unsigned int* s_bits = sm;                    // TILE
    unsigned int* s_cnt  = sm + TILE;             // NBUCK
    unsigned int* s_base = sm + TILE + NBUCK;     // NBUCK
    unsigned int* s_cnt2 = sm + TILE + 2u*NBUCK;  // NBUCK

    unsigned int seg    = blockIdx.x >> 4;        // 16 blocks per segment
    uint2        key    = sks.sk[seg];
    unsigned int base_i = (blockIdx.x * TILE) & SMASK;   // offset within segment

    for (unsigned int b = threadIdx.x; b < NBUCK; b += SCAT_T) { s_cnt[b] = 0u; s_cnt2[b] = 0u; }
    __syncthreads();

    for (unsigned int k = 0; k < TILE; k += SCAT_T) {
        unsigned int i   = k + threadIdx.x;
        unsigned int idx = base_i + i;
        uint32_t o0, o1;
        tf2x32(key.x, key.y, 0u, idx, o0, o1);
        unsigned int bits = o0 ^ o1;
        s_bits[i] = bits;
        atomicAdd(&s_cnt[bits >> (32 - HB)], 1u);
    }
    __syncthreads();

    for (unsigned int b = threadIdx.x; b < NBUCK; b += SCAT_T)
        s_base[b] = atomicAdd(&gcnt[(seg << HB) | b], s_cnt[b]);
    __syncthreads();

    for (unsigned int k = 0; k < TILE; k += SCAT_T) {
        unsigned int i    = k + threadIdx.x;
        unsigned int idx  = base_i + i;
        unsigned int bits = s_bits[i];
        unsigned int b    = bits >> (32 - HB);
        unsigned int lr   = atomicAdd(&s_cnt2[b], 1u);
        unsigned int slot = s_base[b] + lr;
        if (slot < CAP) {
            size_t bucket = (size_t)((seg << HB) | b);
            // pack (low21 bits | idx18): unique per element -> total order
            scratch[(bucket << 8) | slot] =
                (((unsigned long long)(bits & 0x1FFFFFu)) << 18) | idx;
        }
    }
}

// Per-bucket smem bitonic-256 sort; writes the realized permutation (idx) out.
__global__ void bucket_sort_kernel(const unsigned long long* __restrict__ scratch,
                                   const unsigned int* __restrict__ gcnt,
                                   const unsigned int* __restrict__ goff,
                                   unsigned int* __restrict__ pi)
{
    __shared__ unsigned long long arr[CAP];
    unsigned int bid = blockIdx.x;
    unsigned int cnt = gcnt[bid]; if (cnt > CAP) cnt = CAP;
    unsigned int out = goff[bid];
    size_t sbase = ((size_t)bid) << 8;

    for (unsigned int s = threadIdx.x; s < CAP; s += 128u)
        arr[s] = (s < cnt) ? scratch[sbase + s] : ~0ull;
    __syncthreads();

    for (unsigned int k = 2; k <= CAP; k <<= 1) {
        for (unsigned int j = k >> 1; j > 0; j >>= 1) {
            for (unsigned int i = threadIdx.x; i < CAP; i += 128u) {
                unsigned int l = i ^ j;
                if (l > i) {
                    bool up = ((i & k) == 0u);
                    unsigned long long a = arr[i], b = arr[l];
                    if ((a > b) == up) { arr[i] = b; arr[l] = a; }
                }
            }
            __syncthreads();
        }
    }

    for (unsigned int s = threadIdx.x; s < cnt; s += 128u)
        pi[out + s] = (unsigned int)arr[s] & SMASK;
}

// ---------------------------------------------------------------------------
// Accumulation: labels are NOT shuffled; shuffled[i] = pred[pi1[pi2[i]]].
// ---------------------------------------------------------------------------
__global__ void zero_acc()
{
    unsigned int t = threadIdx.x;
    if (t < BATCH) { g_sum2[t] = 0ull; g_npos[t] = 0u; }
}

__global__ void accum_kernel(const unsigned int* __restrict__ pi2,
                             const unsigned int* __restrict__ pi1,
                             const unsigned int* __restrict__ rank2,
                             const int* __restrict__ truth)
{
    unsigned int j = blockIdx.x * blockDim.x + threadIdx.x;
    unsigned long long r = 0ull;
    unsigned int c = 0u;
    if (truth[j] > 0) {
        unsigned int p2   = pi2[j];                 // pi2(i)
        unsigned int base = j & ~SMASK;             // seg * n
        unsigned int orig = pi1[base | p2];         // pi1(pi2(i))
        r = (unsigned long long)rank2[base | orig];
        c = 1u;
    }
    #pragma unroll
    for (int o = 16; o > 0; o >>= 1) {
        r += __shfl_down_sync(0xffffffffu, r, o);
        c += __shfl_down_sync(0xffffffffu, c, o);
    }
    __shared__ unsigned long long sr[8];
    __shared__ unsigned int      sc[8];
    unsigned int w = threadIdx.x >> 5, l = threadIdx.x & 31u;
    if (l == 0u) { sr[w] = r; sc[w] = c; }
    __syncthreads();
    if (threadIdx.x == 0u) {
        unsigned long long R = 0ull; unsigned int C = 0u;
        #pragma unroll
        for (int i = 0; i < 8; ++i) { R += sr[i]; C += sc[i]; }
        unsigned int b = j >> LOGN;   // blockDim=256 divides 2^18: block is seg-pure
        atomicAdd(&g_sum2[b], R);
        atomicAdd(&g_npos[b], C);
    }
}

__global__ void finalize_kernel(float* __restrict__ out)
{
    int b = threadIdx.x;
    __shared__ double sh[BATCH];
    double auc = 0.0;
    if (b < BATCH) {
        double np  = (double)g_npos[b];
        double nn  = (double)NPS - np;
        double spr = 0.5 * (double)g_sum2[b];       // sum of positive ranks (exact)
        auc = (spr - np * (np + 1.0) * 0.5) / (np * nn);
    }
    sh[b] = auc;
    __syncthreads();
    if (b == 0) {
        double s = 0.0;
        for (int i = 0; i < BATCH; ++i) s += sh[i];
        out[0] = (float)(s / (double)BATCH);
    }
}

// ---------------------------------------------------------------------------
// Host launch: forked capture — stream 0 runs the CUB rank sort, a
// non-blocking side stream runs the custom shuffle realization.
// ---------------------------------------------------------------------------
static void run_shuffle_round(cudaStream_t s, const SubKeys& sk,
                              unsigned long long* dScratch,
                              unsigned int* dCnt, unsigned int* dOff,
                              void* dTemp2, unsigned int* dPi)
{
    zero_u32<<<(TOTBUCK + 255) / 256, 256, 0, s>>>(dCnt, TOTBUCK);
    scatter_kernel<<<TOTN / TILE, SCAT_T, (TILE + 3u * NBUCK) * sizeof(unsigned int), s>>>(
        sk, dScratch, dCnt);
    size_t tb2 = sizeof(g_temp2);
    cub::DeviceScan::ExclusiveSum(dTemp2, tb2, dCnt, dOff, (int)TOTBUCK, s);
    bucket_sort_kernel<<<TOTBUCK, 128, 0, s>>>(dScratch, dCnt, dOff, dPi);
}

extern "C" void kernel_launch(void* const* d_in, const int* in_sizes, int n_in,
                              void* d_out, int out_size)
{
    (void)in_sizes; (void)n_in; (void)out_size;
    const float* pred  = (const float*)d_in[0];
    const int*   truth = (const int*)d_in[1];
    float*       out   = (float*)d_out;

    // Per-sample shuffle subkeys (partitionable threefry, seed 42) — verified
    // bit-exact (rel_err 0.0).
    SubKeys s1, s2;
    for (int b = 0; b < BATCH; ++b) {
        uint32_t kb0, kb1, nk0, nk1, a0, a1;
        tf2x32(0u, 42u, 0u, (uint32_t)b, kb0, kb1);   // sample key
        tf2x32(kb0, kb1, 0u, 0u, nk0, nk1);           // carried key after round-1 split
        tf2x32(kb0, kb1, 0u, 1u, a0, a1);             // round-1 subkey
        s1.sk[b] = make_uint2(a0, a1);
        tf2x32(nk0, nk1, 0u, 1u, a0, a1);             // round-2 subkey
        s2.sk[b] = make_uint2(a0, a1);
    }

    unsigned long long *dA, *dB, *dScratch;
    unsigned int *dRank, *dPi1, *dPi2, *dCnt, *dOff;
    void *dTemp, *dTemp2;
    cudaGetSymbolAddress((void**)&dA, g_bufA);
    cudaGetSymbolAddress((void**)&dB, g_bufB);
    cudaGetSymbolAddress((void**)&dScratch, g_scratch);
    cudaGetSymbolAddress((void**)&dRank, g_rank2);
    cudaGetSymbolAddress((void**)&dPi1, g_pi1);
    cudaGetSymbolAddress((void**)&dPi2, g_pi2);
    cudaGetSymbolAddress((void**)&dCnt, g_cnt);
    cudaGetSymbolAddress((void**)&dOff, g_off);
    cudaGetSymbolAddress(&dTemp, g_temp);
    cudaGetSymbolAddress(&dTemp2, g_temp2);

    cudaFuncSetAttribute(scatter_kernel, cudaFuncAttributeMaxDynamicSharedMemorySize,
                         (int)((TILE + 3u * NBUCK) * sizeof(unsigned int)));

    // Fork: side stream + events (created fresh each call; never destroyed while
    // capture may reference them — kernel_launch is only invoked a few times).
    cudaStream_t sB;
    cudaStreamCreateWithFlags(&sB, cudaStreamNonBlocking);
    cudaEvent_t eFork, eJoin;
    cudaEventCreateWithFlags(&eFork, cudaEventDisableTiming);
    cudaEventCreateWithFlags(&eJoin, cudaEventDisableTiming);

    cudaEventRecord(eFork, 0);
    cudaStreamWaitEvent(sB, eFork, 0);

    // ---- Branch B (side stream): realize pi1, pi2 via 2-pass MSD sort ------
    run_shuffle_round(sB, s1, dScratch, dCnt, dOff, dTemp2, dPi1);
    run_shuffle_round(sB, s2, dScratch, dCnt, dOff, dTemp2, dPi2);
    cudaEventRecord(eJoin, sB);

    // ---- Branch A (stream 0): per-sample tie-averaged ranks of pred --------
    const int TPB = 256;
    const unsigned int GRID = TOTN / TPB;   // 65536
    gen_rank_keys<<<GRID, TPB>>>(pred, dA);
    {
        cub::DoubleBuffer<unsigned long long> db(dA, dB);
        size_t tb = sizeof(g_temp);
        cub::DeviceRadixSort::SortKeys(dTemp, tb, db, (int)TOTN, 18, 56);
        rank_kernel<<<GRID, TPB>>>(db.Current(), dRank);
    }

    // ---- Join + exact integer AUC accumulation + mean ----------------------
    cudaStreamWaitEvent(0, eJoin, 0);
    zero_acc<<<1, BATCH>>>();
    accum_kernel<<<GRID, TPB>>>(dPi2, dPi1, dRank, truth);
    finalize_kernel<<<1, BATCH>>>(out);
}

// round 7
// speedup vs baseline: 1.3224x; 1.3224x over previous
#include <cuda_runtime.h>
#include <cuda_bf16.h>
#include <cstdint>
#include <cub/cub.cuh>

// Problem geometry: B=64 samples, n = 512*512 = 2^18 elements per sample.
#define BATCH 64
#define LOGN  18
#define NPS   (1u << LOGN)              // 262144
#define SMASK (NPS - 1u)                // 0x3FFFF
#define TOTN  (BATCH * NPS)             // 16777216

// Counting-rank config for the uniform shuffle bits: 16-bit prefix buckets.
#define CB        16
#define NCB       (1u << CB)            // 65536 buckets per segment
#define TOTCB     (BATCH * NCB)         // 4.2M counters (16 MB, L2-resident)

// ---------------------------------------------------------------------------
// Static device scratch (allocation-free per harness rules).
// ---------------------------------------------------------------------------
__device__ __align__(256) unsigned long long g_bufA[TOTN];   // 128 MB (rank sort)
__device__ __align__(256) unsigned long long g_bufB[TOTN];   // 128 MB (rank sort alt)
__device__ __align__(256) unsigned long long g_rec [TOTN];   // 134 MB bucket records
__device__ __align__(256) unsigned int       g_bits[TOTN];   //  64 MB raw threefry bits
__device__ __align__(256) unsigned int       g_rank2[TOTN];  //  64 MB 2*avg_rank per orig idx
__device__ __align__(256) unsigned int       g_inv1[TOTN];   //  64 MB inv-perm round 1
__device__ __align__(256) unsigned int       g_inv2[TOTN];   //  64 MB inv-perm round 2
__device__ __align__(256) unsigned int       g_cnt[TOTCB];   //  16 MB counts / cursors
__device__ __align__(256) unsigned int       g_off[TOTCB];   //  16 MB scanned offsets
__device__ __align__(256) unsigned int       g_tmask[TOTN/32]; // 2 MB label bitmask
__device__ __align__(256) unsigned char      g_temp [64u*1024u*1024u]; // CUB radix temp
__device__ __align__(256) unsigned char      g_temp2[ 4u*1024u*1024u]; // CUB scan temp
__device__ unsigned long long g_sum2[BATCH];
__device__ unsigned int       g_npos[BATCH];

struct SubKeys { uint2 sk[BATCH]; };

// ---------------------------------------------------------------------------
// Threefry-2x32 (20 rounds), matches JAX's threefry2x32_p.
// ---------------------------------------------------------------------------
__host__ __device__ __forceinline__ void tf2x32(uint32_t k0, uint32_t k1,
                                                uint32_t x0, uint32_t x1,
                                                uint32_t& o0, uint32_t& o1)
{
    uint32_t ks2 = k0 ^ k1 ^ 0x1BD11BDAu;
    x0 += k0; x1 += k1;
#define TFR(r) { x0 += x1; x1 = (x1 << (r)) | (x1 >> (32 - (r))); x1 ^= x0; }
    TFR(13) TFR(15) TFR(26) TFR(6)
    x0 += k1;  x1 += ks2 + 1u;
    TFR(17) TFR(29) TFR(16) TFR(24)
    x0 += ks2; x1 += k0 + 2u;
    TFR(13) TFR(15) TFR(26) TFR(6)
    x0 += k0;  x1 += k1 + 3u;
    TFR(17) TFR(29) TFR(16) TFR(24)
    x0 += k1;  x1 += ks2 + 4u;
    TFR(13) TFR(15) TFR(26) TFR(6)
    x0 += ks2; x1 += k0 + 5u;
#undef TFR
    o0 = x0; o1 = x1;
}

// ---------------------------------------------------------------------------
// Branch A: rank phase (unchanged — verified bit-exact, rel_err 0.0).
// ---------------------------------------------------------------------------
__global__ void gen_rank_keys(const float* __restrict__ pred,
                              unsigned long long* __restrict__ out)
{
    unsigned int j = blockIdx.x * blockDim.x + threadIdx.x;
    uint32_t u = __float_as_uint(pred[j]);
    u = (u >> 31) ? ~u : (u | 0x80000000u);   // totally-ordered ascending float bits
    unsigned long long seg = (unsigned long long)(j >> LOGN);
    out[j] = (seg << 50) | ((unsigned long long)u << 18) | (j & SMASK);
}

__global__ void rank_kernel(const unsigned long long* __restrict__ KR,
                            unsigned int* __restrict__ rank2)
{
    unsigned int j = blockIdx.x * blockDim.x + threadIdx.x;
    unsigned long long k = KR[j];
    unsigned long long hk = k >> 18;          // seg+value bits: runs never cross segments
    unsigned int s = j, e = j;
    while (s > 0u && (KR[s - 1u] >> 18) == hk) --s;       // ties rare & short
    while (e + 1u < TOTN && (KR[e + 1u] >> 18) == hk) ++e;
    unsigned int orig = (unsigned int)k & SMASK;
    unsigned int twice_rank = (s & SMASK) + (e & SMASK) + 2u;
    rank2[(j & ~SMASK) | orig] = twice_rank;
}

// ---------------------------------------------------------------------------
// Branch B: inverse permutations of the shuffles via counting-rank.
// invpi[j] = rank of bits[j] within its segment (stable tie-break by index),
// computed with a 16-bit-prefix counting sort (uniform keys => tiny buckets).
// ---------------------------------------------------------------------------
__global__ void zero_cnt(unsigned int* __restrict__ p)
{
    unsigned int i = blockIdx.x * blockDim.x + threadIdx.x;
    if (i < TOTCB) p[i] = 0u;
}

__global__ void gen_hist(SubKeys sks,
                         unsigned int* __restrict__ bits,
                         unsigned int* __restrict__ cnt)
{
    unsigned int j = blockIdx.x * blockDim.x + threadIdx.x;
    unsigned int seg = j >> LOGN, i = j & SMASK;
    uint2 k = sks.sk[seg];
    uint32_t o0, o1;
    tf2x32(k.x, k.y, 0u, i, o0, o1);
    uint32_t b32 = o0 ^ o1;
    bits[j] = b32;
    atomicAdd(&cnt[(seg << CB) | (b32 >> (32 - CB))], 1u);
}

__global__ void scatter_rec(const unsigned int* __restrict__ bits,
                            const unsigned int* __restrict__ off,
                            unsigned int* __restrict__ cursor,
                            unsigned long long* __restrict__ rec)
{
    unsigned int j = blockIdx.x * blockDim.x + threadIdx.x;
    unsigned int seg = j >> LOGN, i = j & SMASK;
    unsigned int b32 = bits[j];
    unsigned int b = (seg << CB) | (b32 >> (32 - CB));
    unsigned int slot = atomicAdd(&cursor[b], 1u);
    // record: (low16 of bits << 18) | pos  — unique key, JAX-stable tie order
    rec[off[b] + slot] = (((unsigned long long)(b32 & 0xFFFFu)) << 18) | i;
}

__global__ void bucket_rank(const unsigned long long* __restrict__ rec,
                            const unsigned int* __restrict__ off,
                            const unsigned int* __restrict__ cnt,
                            unsigned int* __restrict__ inv)
{
    unsigned int b = blockIdx.x * blockDim.x + threadIdx.x;
    if (b >= TOTCB) return;
    unsigned int k = cnt[b];
    if (k == 0u) return;
    unsigned int base = off[b];
    unsigned int seg  = b >> CB;
    unsigned int baserank = base - seg * NPS;     // scan is segment-major
    unsigned int segbase  = seg << LOGN;
    if (k == 1u) {                                 // common case (Poisson(4) tail)
        unsigned long long rx = rec[base];
        inv[segbase + ((unsigned int)rx & SMASK)] = baserank;
        return;
    }
    for (unsigned int x = 0; x < k; ++x) {
        unsigned long long rx = rec[base + x];
        unsigned int r = 0u;
        for (unsigned int y = 0; y < k; ++y)
            r += (rec[base + y] < rx) ? 1u : 0u;
        inv[segbase + ((unsigned int)rx & SMASK)] = baserank + r;
    }
}

// ---------------------------------------------------------------------------
// Labels: pack t>0 into a 2 MB bitmask (L2-resident for the final gather) and
// count positives per segment.
// ---------------------------------------------------------------------------
__global__ void zero_acc()
{
    unsigned int t = threadIdx.x;
    if (t < BATCH) { g_sum2[t] = 0ull; g_npos[t] = 0u; }
}

__global__ void pack_truth(const int* __restrict__ truth,
                           unsigned int* __restrict__ tmask)
{
    unsigned int j = blockIdx.x * blockDim.x + threadIdx.x;
    unsigned int bit = (truth[j] > 0) ? 1u : 0u;
    unsigned int ballot = __ballot_sync(0xffffffffu, bit);
    if ((threadIdx.x & 31u) == 0u) {
        tmask[j >> 5] = ballot;
        atomicAdd(&g_npos[j >> LOGN], (unsigned int)__popc(ballot));
    }
}

// ---------------------------------------------------------------------------
// Accumulation over ORIGINAL indices:
//   sum2[seg] += rank2[j] * t[ inv2[ inv1[j] ] ]
// ---------------------------------------------------------------------------
__global__ void accum_kernel(const unsigned int* __restrict__ inv1,
                             const unsigned int* __restrict__ inv2,
                             const unsigned int* __restrict__ rank2,
                             const unsigned int* __restrict__ tmask)
{
    unsigned int j = blockIdx.x * blockDim.x + threadIdx.x;
    unsigned int segbase = j & ~SMASK;
    unsigned int p  = inv2[segbase | inv1[j]];      // final position of element j
    unsigned int gb = segbase | p;                  // global bit index
    unsigned int bit = (tmask[gb >> 5] >> (gb & 31u)) & 1u;
    unsigned long long r = bit ? (unsigned long long)rank2[j] : 0ull;
    #pragma unroll
    for (int o = 16; o > 0; o >>= 1)
        r += __shfl_down_sync(0xffffffffu, r, o);
    __shared__ unsigned long long sr[8];
    unsigned int w = threadIdx.x >> 5, l = threadIdx.x & 31u;
    if (l == 0u) sr[w] = r;
    __syncthreads();
    if (threadIdx.x == 0u) {
        unsigned long long R = 0ull;
        #pragma unroll
        for (int i = 0; i < 8; ++i) R += sr[i];
        atomicAdd(&g_sum2[j >> LOGN], R);           // block is segment-pure
    }
}

__global__ void finalize_kernel(float* __restrict__ out)
{
    int b = threadIdx.x;
    __shared__ double sh[BATCH];
    double auc = 0.0;
    if (b < BATCH) {
        double np  = (double)g_npos[b];
        double nn  = (double)NPS - np;
        double spr = 0.5 * (double)g_sum2[b];       // sum of positive ranks (exact)
        auc = (spr - np * (np + 1.0) * 0.5) / (np * nn);
    }
    sh[b] = auc;
    __syncthreads();
    if (b == 0) {
        double s = 0.0;
        for (int i = 0; i < BATCH; ++i) s += sh[i];
        out[0] = (float)(s / (double)BATCH);
    }
}

// ---------------------------------------------------------------------------
// Host launch: forked capture — stream 0 runs the CUB rank sort (critical
// path), a non-blocking side stream realizes both inverse shuffles.
// ---------------------------------------------------------------------------
static void run_inv_round(cudaStream_t s, const SubKeys& sk,
                          unsigned int* dBits, unsigned long long* dRec,
                          unsigned int* dCnt, unsigned int* dOff,
                          void* dTemp2, unsigned int* dInv)
{
    const unsigned int ZGRID = (TOTCB + 255u) / 256u;
    zero_cnt<<<ZGRID, 256, 0, s>>>(dCnt);
    gen_hist<<<TOTN / 256, 256, 0, s>>>(sk, dBits, dCnt);
    size_t tb2 = sizeof(g_temp2);
    cub::DeviceScan::ExclusiveSum(dTemp2, tb2, dCnt, dOff, (int)TOTCB, s);
    zero_cnt<<<ZGRID, 256, 0, s>>>(dCnt);                   // reuse as cursor
    scatter_rec<<<TOTN / 256, 256, 0, s>>>(dBits, dOff, dCnt, dRec);
    bucket_rank<<<ZGRID, 256, 0, s>>>(dRec, dOff, dCnt, dInv);
}

extern "C" void kernel_launch(void* const* d_in, const int* in_sizes, int n_in,
                              void* d_out, int out_size)
{
    (void)in_sizes; (void)n_in; (void)out_size;
    const float* pred  = (const float*)d_in[0];
    const int*   truth = (const int*)d_in[1];
    float*       out   = (float*)d_out;

    // Per-sample shuffle subkeys (partitionable threefry, seed 42) — verified
    // bit-exact (rel_err 0.0 in prior rounds).
    SubKeys s1, s2;
    for (int b = 0; b < BATCH; ++b) {
        uint32_t kb0, kb1, nk0, nk1, a0, a1;
        tf2x32(0u, 42u, 0u, (uint32_t)b, kb0, kb1);   // sample key
        tf2x32(kb0, kb1, 0u, 0u, nk0, nk1);           // carried key after round-1 split
        tf2x32(kb0, kb1, 0u, 1u, a0, a1);             // round-1 subkey
        s1.sk[b] = make_uint2(a0, a1);
        tf2x32(nk0, nk1, 0u, 1u, a0, a1);             // round-2 subkey
        s2.sk[b] = make_uint2(a0, a1);
    }

    unsigned long long *dA, *dB, *dRec;
    unsigned int *dRank, *dBits, *dInv1, *dInv2, *dCnt, *dOff, *dTmask;
    void *dTemp, *dTemp2;
    cudaGetSymbolAddress((void**)&dA, g_bufA);
    cudaGetSymbolAddress((void**)&dB, g_bufB);
    cudaGetSymbolAddress((void**)&dRec, g_rec);
    cudaGetSymbolAddress((void**)&dRank, g_rank2);
    cudaGetSymbolAddress((void**)&dBits, g_bits);
    cudaGetSymbolAddress((void**)&dInv1, g_inv1);
    cudaGetSymbolAddress((void**)&dInv2, g_inv2);
    cudaGetSymbolAddress((void**)&dCnt, g_cnt);
    cudaGetSymbolAddress((void**)&dOff, g_off);
    cudaGetSymbolAddress((void**)&dTmask, g_tmask);
    cudaGetSymbolAddress(&dTemp, g_temp);
    cudaGetSymbolAddress(&dTemp2, g_temp2);

    // Fork: side stream + events, created fresh per call (never destroyed
    // while the captured graph may reference them).
    cudaStream_t sB;
    cudaStreamCreateWithFlags(&sB, cudaStreamNonBlocking);
    cudaEvent_t eFork, eJoin;
    cudaEventCreateWithFlags(&eFork, cudaEventDisableTiming);
    cudaEventCreateWithFlags(&eJoin, cudaEventDisableTiming);

    cudaEventRecord(eFork, 0);
    cudaStreamWaitEvent(sB, eFork, 0);

    // ---- Branch B (side stream): labels + both inverse shuffles ------------
    zero_acc<<<1, BATCH, 0, sB>>>();
    pack_truth<<<TOTN / 256, 256, 0, sB>>>(truth, dTmask);
    run_inv_round(sB, s1, dBits, dRec, dCnt, dOff, dTemp2, dInv1);
    run_inv_round(sB, s2, dBits, dRec, dCnt, dOff, dTemp2, dInv2);
    cudaEventRecord(eJoin, sB);

    // ---- Branch A (stream 0): per-sample tie-averaged ranks of pred --------
    const int TPB = 256;
    const unsigned int GRID = TOTN / TPB;   // 65536
    gen_rank_keys<<<GRID, TPB>>>(pred, dA);
    {
        cub::DoubleBuffer<unsigned long long> db(dA, dB);
        size_t tb = sizeof(g_temp);
        cub::DeviceRadixSort::SortKeys(dTemp, tb, db, (int)TOTN, 18, 56);
        rank_kernel<<<GRID, TPB>>>(db.Current(), dRank);
    }

    // ---- Join + exact integer AUC accumulation + mean ----------------------
    cudaStreamWaitEvent(0, eJoin, 0);
    accum_kernel<<<GRID, TPB>>>(dInv1, dInv2, dRank, dTmask);
    finalize_kernel<<<1, BATCH>>>(out);
}